// round 16
// baseline (speedup 1.0000x reference)
#include <cuda_runtime.h>
#include <cstdint>

// Nearest codeword on grid g_i = i - 7.5, i in [0,15]:
//   g(x) = clamp(ceil(x) - 0.5, -7.5, 7.5)  (ties -> lower codeword, matches argmax)
//   idx  = g + 7.5
__device__ __forceinline__ void quant1(float x, float& g, float& id) {
    float q = ceilf(x) - 0.5f;
    q = fminf(fmaxf(q, -7.5f), 7.5f);
    g = q;
    id = q + 7.5f;
}

__device__ __forceinline__ float4 quant4_vals(float4 v, float4& id) {
    float4 g;
    quant1(v.x, g.x, id.x);
    quant1(v.y, g.y, id.y);
    quant1(v.z, g.z, id.z);
    quant1(v.w, g.w, id.w);
    return g;
}

// sm_103a requires 256-bit type for L2::evict_last loads (.v4.b64) — ptxas told
// us so in R14. One instruction loads 32 bytes (two float4s) with evict-last
// bias, keeping the 32MB input L2-resident across graph replays in the normal
// ways (no persisting-carveout lottery).
__device__ __forceinline__ void ldg256_evict_last(const float4* p,
                                                  float4& a, float4& b) {
    unsigned long long r0, r1, r2, r3;
    asm volatile("ld.global.nc.L2::evict_last.v4.b64 {%0,%1,%2,%3}, [%4];"
                 : "=l"(r0), "=l"(r1), "=l"(r2), "=l"(r3)
                 : "l"(p));
    a.x = __uint_as_float((unsigned)(r0));
    a.y = __uint_as_float((unsigned)(r0 >> 32));
    a.z = __uint_as_float((unsigned)(r1));
    a.w = __uint_as_float((unsigned)(r1 >> 32));
    b.x = __uint_as_float((unsigned)(r2));
    b.y = __uint_as_float((unsigned)(r2 >> 32));
    b.z = __uint_as_float((unsigned)(r3));
    b.w = __uint_as_float((unsigned)(r3 >> 32));
}

// Each thread: CHUNKS x 32B loads (block-strided) = 4 float4s of work, matching
// the measured-optimal 2048x256 shape. Outputs: __stcs evict-first STG.128.
constexpr int CHUNKS = 2;

__global__ void __launch_bounds__(256) quant_kernel_f32f32(
    const float4* __restrict__ x,
    float4* __restrict__ vals,
    float4* __restrict__ idxf,
    int n8) {           // number of 32B chunks
    int base = blockIdx.x * (blockDim.x * CHUNKS) + threadIdx.x;
    int stride = blockDim.x;

    float4 a[CHUNKS], b[CHUNKS];
#pragma unroll
    for (int k = 0; k < CHUNKS; k++) {
        int c = base + k * stride;
        ldg256_evict_last(&x[2 * c], a[k], b[k]);
    }
#pragma unroll
    for (int k = 0; k < CHUNKS; k++) {
        int c = base + k * stride;
        float4 ida, idb;
        float4 ga = quant4_vals(a[k], ida);
        float4 gb = quant4_vals(b[k], idb);
        __stcs(&vals[2 * c],     ga);
        __stcs(&vals[2 * c + 1], gb);
        __stcs(&idxf[2 * c],     ida);
        __stcs(&idxf[2 * c + 1], idb);
    }
}

// Fallback paths (other output layouts), kept for safety.
__global__ void quant_kernel_f32u8(const float4* __restrict__ x,
                                   float4* __restrict__ vals,
                                   uchar4* __restrict__ idxb,
                                   int n4) {
    int i = blockIdx.x * blockDim.x + threadIdx.x;
    if (i >= n4) return;
    float4 id;
    float4 g = quant4_vals(x[i], id);
    __stcs(&vals[i], g);
    idxb[i] = make_uchar4((unsigned char)id.x, (unsigned char)id.y,
                          (unsigned char)id.z, (unsigned char)id.w);
}

__global__ void quant_kernel_valsonly(const float4* __restrict__ x,
                                      float4* __restrict__ vals,
                                      int n4) {
    int i = blockIdx.x * blockDim.x + threadIdx.x;
    if (i >= n4) return;
    float4 id;
    float4 g = quant4_vals(x[i], id);
    __stcs(&vals[i], g);
}

extern "C" void kernel_launch(void* const* d_in, const int* in_sizes, int n_in,
                              void* d_out, int out_size) {
    const float* x = (const float*)d_in[0];
    int n = in_sizes[0];           // 8388608
    int n4 = n >> 2;               // 2M float4s
    int n8 = n >> 3;               // 1M 32B chunks
    const int threads = 256;

    if (out_size == 2 * n && (n8 % (threads * CHUNKS)) == 0) {
        float* out = (float*)d_out;
        int blocks = n8 / (threads * CHUNKS);   // 2048
        quant_kernel_f32f32<<<blocks, threads>>>(
            (const float4*)x, (float4*)out, (float4*)(out + n), n8);
    } else if (out_size == 5 * n) {
        uint8_t* out = (uint8_t*)d_out;
        int blocks = (n4 + threads - 1) / threads;
        quant_kernel_f32u8<<<blocks, threads>>>(
            (const float4*)x, (float4*)out, (uchar4*)(out + (size_t)4 * n), n4);
    } else {
        int blocks = (n4 + threads - 1) / threads;
        quant_kernel_valsonly<<<blocks, threads>>>(
            (const float4*)x, (float4*)d_out, n4);
    }
}